// round 15
// baseline (speedup 1.0000x reference)
#include <cuda_runtime.h>
#include <cuda_bf16.h>
#include <cuda_fp16.h>
#include <stdint.h>

// ---------------------------------------------------------------------------
// Problem dims
// ---------------------------------------------------------------------------
static const int cNS  = 8192;
static const int cNK  = 8192;
static const int cHID = 1024;
static const int cKED = 2048;
static const int CHUNKS = 64;  // softmax row chunks = one 128-row CTA tile each

// fp8 lo-plane scale (2^12) to dodge e4m3 underflow; folded back at the end.
static const float FP8_SCALE    = 4096.0f;
static const float FP8_INVSCALE = 1.0f / 4096.0f;

// ---------------------------------------------------------------------------
// Scratch (__device__ globals; allocation-free)
// ---------------------------------------------------------------------------
__device__ __nv_bfloat16 g_Xs_h[(size_t)cNS * cHID];
__device__ __nv_bfloat16 g_Xs_l[(size_t)cNS * cHID];
__device__ __nv_bfloat16 g_Xk_h[(size_t)cNK * cKED];
__device__ __nv_bfloat16 g_Xk_l[(size_t)cNK * cKED];
__device__ __nv_bfloat16 g_Ws_h[(size_t)cHID * cHID];
__device__ __nv_bfloat16 g_Ws_l[(size_t)cHID * cHID];
__device__ __nv_bfloat16 g_Wk_h[(size_t)cHID * cKED];
__device__ __nv_bfloat16 g_Wk_l[(size_t)cHID * cKED];
__device__ __half   g_S_h [(size_t)cNS * cHID];    // S hi plane fp16
__device__ uint8_t  g_S_h8[(size_t)cNS * cHID];    // S hi plane fp8 (e4m3)
__device__ uint8_t  g_S_l8[(size_t)cNS * cHID];    // S lo plane fp8 (x4096)
__device__ __half   g_K_h [(size_t)cNK * cHID];    // K hi plane fp16
__device__ uint8_t  g_K_h8[(size_t)cNK * cHID];    // K hi plane fp8
__device__ uint8_t  g_K_l8[(size_t)cNK * cHID];    // K lo plane fp8 (x4096)
__device__ __half g_VT[(size_t)cKED * cNK];        // V^T fp16 [2048, 8192]
__device__ __half g_At[(size_t)cNS * cNK];         // attns fp16 (single plane)
__device__ float g_pm[(size_t)CHUNKS * cNK];
__device__ float g_ps[(size_t)CHUNKS * cNK];
__device__ float g_m[cNK];
__device__ float g_rs[cNK];

// ---------------------------------------------------------------------------
// Helpers
// ---------------------------------------------------------------------------
__device__ __forceinline__ uint32_t smem_to_u32(const void* p) {
    uint32_t a;
    asm("{ .reg .u64 t; cvta.to.shared.u64 t, %1; cvt.u32.u64 %0, t; }"
        : "=r"(a) : "l"(p));
    return a;
}

__device__ __forceinline__ void cp_async16(uint32_t smem_addr, const void* gptr) {
    asm volatile("cp.async.cg.shared.global [%0], [%1], 16;\n"
                 :: "r"(smem_addr), "l"(__cvta_generic_to_global(gptr)));
}
__device__ __forceinline__ void cp_commit() {
    asm volatile("cp.async.commit_group;\n" ::: "memory");
}
template <int N>
__device__ __forceinline__ void cp_wait() {
    asm volatile("cp.async.wait_group %0;\n" :: "n"(N) : "memory");
}

__device__ __forceinline__ void ldsm_x4(uint32_t (&r)[4], uint32_t addr) {
    asm volatile("ldmatrix.sync.aligned.m8n8.x4.shared.b16 {%0,%1,%2,%3}, [%4];\n"
                 : "=r"(r[0]), "=r"(r[1]), "=r"(r[2]), "=r"(r[3]) : "r"(addr));
}

// bf16 in, fp32 acc
__device__ __forceinline__ void mma16816(float (&c)[4], const uint32_t (&a)[4],
                                         uint32_t b0, uint32_t b1) {
    asm volatile(
        "mma.sync.aligned.m16n8k16.row.col.f32.bf16.bf16.f32 "
        "{%0,%1,%2,%3}, {%4,%5,%6,%7}, {%8,%9}, {%0,%1,%2,%3};\n"
        : "+f"(c[0]), "+f"(c[1]), "+f"(c[2]), "+f"(c[3])
        : "r"(a[0]), "r"(a[1]), "r"(a[2]), "r"(a[3]), "r"(b0), "r"(b1));
}

// fp16 in, fp32 acc
__device__ __forceinline__ void mma16816h(float (&c)[4], const uint32_t (&a)[4],
                                          uint32_t b0, uint32_t b1) {
    asm volatile(
        "mma.sync.aligned.m16n8k16.row.col.f32.f16.f16.f32 "
        "{%0,%1,%2,%3}, {%4,%5,%6,%7}, {%8,%9}, {%0,%1,%2,%3};\n"
        : "+f"(c[0]), "+f"(c[1]), "+f"(c[2]), "+f"(c[3])
        : "r"(a[0]), "r"(a[1]), "r"(a[2]), "r"(a[3]), "r"(b0), "r"(b1));
}

// e4m3 in, fp32 acc, k32 (cross-term passes)
__device__ __forceinline__ void mma16832q(float (&c)[4], const uint32_t (&a)[4],
                                          uint32_t b0, uint32_t b1) {
    asm volatile(
        "mma.sync.aligned.m16n8k32.row.col.f32.e4m3.e4m3.f32 "
        "{%0,%1,%2,%3}, {%4,%5,%6,%7}, {%8,%9}, {%0,%1,%2,%3};\n"
        : "+f"(c[0]), "+f"(c[1]), "+f"(c[2]), "+f"(c[3])
        : "r"(a[0]), "r"(a[1]), "r"(a[2]), "r"(a[3]), "r"(b0), "r"(b1));
}

// pack two floats -> e4m3x2 (e0 -> low byte, e1 -> high byte)
__device__ __forceinline__ uint16_t cvt2_e4m3(float e1, float e0) {
    uint16_t r;
    asm("{\n\t.reg .b16 t;\n\tcvt.rn.satfinite.e4m3x2.f32 t, %1, %2;\n\t"
        "mov.b16 %0, t;\n\t}"
        : "=h"(r) : "f"(e1), "f"(e0));
    return r;
}

__device__ __forceinline__ void split1(float x, __nv_bfloat16& h, __nv_bfloat16& l) {
    h = __float2bfloat16(x);
    l = __float2bfloat16(x - __bfloat162float(h));
}

// ---------------------------------------------------------------------------
// Split / fused split+transpose preprocessing
// ---------------------------------------------------------------------------
__global__ void split_kernel(const float* __restrict__ in,
                             __nv_bfloat16* __restrict__ hi,
                             __nv_bfloat16* __restrict__ lo, size_t n) {
    size_t i = ((size_t)blockIdx.x * 256 + threadIdx.x) * 4;
    if (i >= n) return;
    float4 v = *(const float4*)(in + i);
    __nv_bfloat16 h0, h1, h2, h3, l0, l1, l2, l3;
    split1(v.x, h0, l0); split1(v.y, h1, l1);
    split1(v.z, h2, l2); split1(v.w, h3, l3);
    *(__nv_bfloat162*)(hi + i)     = __nv_bfloat162(h0, h1);
    *(__nv_bfloat162*)(hi + i + 2) = __nv_bfloat162(h2, h3);
    *(__nv_bfloat162*)(lo + i)     = __nv_bfloat162(l0, l1);
    *(__nv_bfloat162*)(lo + i + 2) = __nv_bfloat162(l2, l3);
}

// Read Xk once: emit bf16 hi/lo planes (row-major) + fp16 V^T (transposed).
__global__ void split_transpose_kernel(const float* __restrict__ in,
                                       __nv_bfloat16* __restrict__ hi,
                                       __nv_bfloat16* __restrict__ lo,
                                       __half* __restrict__ vt,
                                       int R, int C) {
    __shared__ float t[32][33];
    int c0 = blockIdx.x * 32, r0 = blockIdx.y * 32;
    int tx = threadIdx.x, ty = threadIdx.y;
#pragma unroll
    for (int j = 0; j < 4; ++j) {
        float v = in[(size_t)(r0 + ty + j * 8) * C + c0 + tx];
        t[ty + j * 8][tx] = v;
        __nv_bfloat16 h, l; split1(v, h, l);
        size_t off = (size_t)(r0 + ty + j * 8) * C + c0 + tx;
        hi[off] = h; lo[off] = l;
    }
    __syncthreads();
#pragma unroll
    for (int j = 0; j < 4; ++j)
        vt[(size_t)(c0 + ty + j * 8) * R + r0 + tx] = __float2half(t[tx][ty + j * 8]);
}

// ---------------------------------------------------------------------------
// Common GEMM geometry: 128x128 CTA tile, BK=32, 3-stage cp.async pipeline,
// 8 warps (2x4), warp tile 64x32, padded SMEM rows (conflict-free ldsm).
// ---------------------------------------------------------------------------
static const int ROWB    = 80;                 // fp16/bf16: 64B data + 16B pad
static const int TILE_B  = 128 * ROWB;         // 10240 B per 16-bit plane-tile
static const int ROW8    = 48;                 // fp8: 32B data + 16B pad
static const int T8B     = 128 * ROW8;         // 6144 B per fp8 plane-tile

static const int STAGE_B3 = 4 * TILE_B;        // proj: Ah, Al, Bh, Bl (bf16)
static const int SMEM_3P  = 3 * STAGE_B3;      // 122880

// === Projection GEMM (bf16 in, fp32 acc, 3 passes): C = (Ah+Al)(Bh+Bl)^T + b
//     Epilogue emits fp16 hi plane + fp8 hi plane + fp8 lo plane (x4096). ===
__global__ __launch_bounds__(256, 1)
void mma_gemm_proj(const __nv_bfloat16* __restrict__ Ah, const __nv_bfloat16* __restrict__ Al,
                   const __nv_bfloat16* __restrict__ Bh, const __nv_bfloat16* __restrict__ Bl,
                   const float* __restrict__ bias,
                   __half* __restrict__ Ch, uint8_t* __restrict__ Ch8,
                   uint8_t* __restrict__ Cl8,
                   int M, int N, int K)
{
    extern __shared__ char sm[];
    const uint32_t sbase = smem_to_u32(sm);

    const int tid = threadIdx.x;
    const int wid = tid >> 5, lane = tid & 31;
    const int wm = wid >> 2, wn = wid & 3;      // 2 x 4 warp grid
    const int row0 = blockIdx.y * 128, col0 = blockIdx.x * 128;

    const __nv_bfloat16* srcs[4] = {
        Ah + (size_t)row0 * K, Al + (size_t)row0 * K,
        Bh + (size_t)col0 * K, Bl + (size_t)col0 * K };

    const int NT = K >> 5;

    auto issue_loads = [&](int kt, int s) {
        const int k0 = kt << 5;
#pragma unroll
        for (int i = 0; i < 8; ++i) {
            int q = tid + i * 256;
            int t = q >> 9, idx = q & 511;
            int row = idx >> 2, c = idx & 3;
            const __nv_bfloat16* g = srcs[t] + (size_t)row * K + k0 + c * 8;
            uint32_t d = sbase + s * STAGE_B3 + t * TILE_B + row * ROWB + c * 16;
            cp_async16(d, g);
        }
    };

    issue_loads(0, 0); cp_commit();
    issue_loads(1, 1); cp_commit();

    float acc[4][4][4];
#pragma unroll
    for (int i = 0; i < 4; ++i)
#pragma unroll
        for (int j = 0; j < 4; ++j)
#pragma unroll
            for (int v = 0; v < 4; ++v) acc[i][j][v] = 0.f;

    const int lrow = lane & 15, lcol = lane >> 4;

    for (int kt = 0; kt < NT; ++kt) {
        const int s = kt % 3;
        cp_wait<1>();
        __syncthreads();
        if (kt + 2 < NT) issue_loads(kt + 2, (kt + 2) % 3);
        cp_commit();

#pragma unroll
        for (int ks = 0; ks < 2; ++ks) {
            uint32_t ah[4][4], al[4][4], bh[2][4], bl[2][4];
            const uint32_t abase = sbase + s * STAGE_B3
                + (wm * 64 + lrow) * ROWB + ks * 32 + lcol * 16;
#pragma unroll
            for (int mi = 0; mi < 4; ++mi) {
                ldsm_x4(ah[mi], abase + mi * 16 * ROWB);
                ldsm_x4(al[mi], abase + mi * 16 * ROWB + TILE_B);
            }
            const uint32_t bbase = sbase + s * STAGE_B3 + 2 * TILE_B
                + (wn * 32 + lrow) * ROWB + ks * 32 + lcol * 16;
#pragma unroll
            for (int bj = 0; bj < 2; ++bj) {
                ldsm_x4(bh[bj], bbase + bj * 16 * ROWB);
                ldsm_x4(bl[bj], bbase + bj * 16 * ROWB + TILE_B);
            }
#pragma unroll
            for (int mi = 0; mi < 4; ++mi) {
#pragma unroll
                for (int jn = 0; jn < 4; ++jn) {
                    const int bj = jn >> 1, hf = jn & 1;
                    mma16816(acc[mi][jn], ah[mi], bh[bj][hf], bh[bj][hf + 2]);
                    mma16816(acc[mi][jn], ah[mi], bl[bj][hf], bl[bj][hf + 2]);
                    mma16816(acc[mi][jn], al[mi], bh[bj][hf], bh[bj][hf + 2]);
                }
            }
        }
    }

    const int g = lane >> 2, cq = (lane & 3) * 2;
#pragma unroll
    for (int mi = 0; mi < 4; ++mi) {
#pragma unroll
        for (int jn = 0; jn < 4; ++jn) {
            const int r0w = row0 + wm * 64 + mi * 16 + g;
            const int cc = col0 + wn * 32 + jn * 8 + cq;
            float b0 = bias[cc], b1 = bias[cc + 1];
            float v0 = acc[mi][jn][0] + b0, v1 = acc[mi][jn][1] + b1;
            float v2 = acc[mi][jn][2] + b0, v3 = acc[mi][jn][3] + b1;
            __half h0 = __float2half(v0), h1 = __float2half(v1);
            __half h2 = __float2half(v2), h3 = __float2half(v3);
            float f0 = __half2float(h0), f1 = __half2float(h1);
            float f2 = __half2float(h2), f3 = __half2float(h3);
            float r0 = (v0 - f0) * FP8_SCALE, r1 = (v1 - f1) * FP8_SCALE;
            float r2 = (v2 - f2) * FP8_SCALE, r3 = (v3 - f3) * FP8_SCALE;
            size_t o0 = (size_t)r0w * N + cc;
            size_t o1 = (size_t)(r0w + 8) * N + cc;
            *(__half2*)(Ch + o0) = __halves2half2(h0, h1);
            *(__half2*)(Ch + o1) = __halves2half2(h2, h3);
            *(uint16_t*)(Ch8 + o0) = cvt2_e4m3(f1, f0);
            *(uint16_t*)(Ch8 + o1) = cvt2_e4m3(f3, f2);
            *(uint16_t*)(Cl8 + o0) = cvt2_e4m3(r1, r0);
            *(uint16_t*)(Cl8 + o1) = cvt2_e4m3(r3, r2);
        }
    }
}

// === Scores GEMM: hh pass fp16/f32-acc (k16 x2); cross passes e4m3 k32
//     into a separate f32 accumulator (x4096 scale, folded at the end).
//     Writes raw fp32 scores; epilogue emits softmax chunk stats. ===
static const int STAGE_SC = 2 * TILE_B + 4 * T8B;   // Ah16,Bh16 + Ah8,Al8,Bh8,Bl8
static const int SMEM_SC  = 3 * STAGE_SC;           // 135168

__global__ __launch_bounds__(256, 1)
void mma_gemm_scores(const __half* __restrict__ Ah, const uint8_t* __restrict__ Ah8,
                     const uint8_t* __restrict__ Al8,
                     const __half* __restrict__ Bh, const uint8_t* __restrict__ Bh8,
                     const uint8_t* __restrict__ Bl8,
                     float* __restrict__ C, int M, int N, int K)
{
    extern __shared__ char sm[];
    const uint32_t sbase = smem_to_u32(sm);

    const int tid = threadIdx.x;
    const int wid = tid >> 5, lane = tid & 31;
    const int wm = wid >> 2, wn = wid & 3;
    const int row0 = blockIdx.y * 128, col0 = blockIdx.x * 128;

    const __half* srcs16[2] = { Ah + (size_t)row0 * K, Bh + (size_t)col0 * K };
    const uint8_t* srcs8[4] = {
        Ah8 + (size_t)row0 * K, Al8 + (size_t)row0 * K,
        Bh8 + (size_t)col0 * K, Bl8 + (size_t)col0 * K };

    const int NT = K >> 5;

    auto issue_loads = [&](int kt, int s) {
        const int k0 = kt << 5;
        const uint32_t sb = sbase + s * STAGE_SC;
#pragma unroll
        for (int i = 0; i < 8; ++i) {
            if (i < 4) {
                int q = tid + i * 256;
                int t = q >> 9, idx = q & 511;
                int row = idx >> 2, c = idx & 3;
                const __half* g = srcs16[t] + (size_t)row * K + k0 + c * 8;
                cp_async16(sb + t * TILE_B + row * ROWB + c * 16, g);
            } else {
                int t = i - 4;                  // 0:Ah8 1:Al8 2:Bh8 3:Bl8
                int row = tid >> 1, c = tid & 1;
                const uint8_t* g = srcs8[t] + (size_t)row * K + k0 + c * 16;
                cp_async16(sb + 2 * TILE_B + t * T8B + row * ROW8 + c * 16, g);
            }
        }
    };

    issue_loads(0, 0); cp_commit();
    issue_loads(1, 1); cp_commit();

    float acc[4][4][4];
    float acc8[4][4][4];
#pragma unroll
    for (int i = 0; i < 4; ++i)
#pragma unroll
        for (int j = 0; j < 4; ++j)
#pragma unroll
            for (int v = 0; v < 4; ++v) { acc[i][j][v] = 0.f; acc8[i][j][v] = 0.f; }

    const int lrow = lane & 15, lcol = lane >> 4;

    for (int kt = 0; kt < NT; ++kt) {
        const int s = kt % 3;
        cp_wait<1>();
        __syncthreads();
        if (kt + 2 < NT) issue_loads(kt + 2, (kt + 2) % 3);
        cp_commit();

        // fp8 cross passes: full k32 per kt, separate scaled accumulator.
        {
            const uint32_t base8 = sbase + s * STAGE_SC + 2 * TILE_B;
            const uint32_t a8hb = base8 + (wm * 64 + lrow) * ROW8 + lcol * 16;
            const uint32_t b8hb = base8 + 2 * T8B + (wn * 32 + lrow) * ROW8 + lcol * 16;
            uint32_t a8[4][4], b8[2][4];
            // pass 1: Ah8 x Bl8
#pragma unroll
            for (int mi = 0; mi < 4; ++mi)
                ldsm_x4(a8[mi], a8hb + mi * 16 * ROW8);
#pragma unroll
            for (int bj = 0; bj < 2; ++bj)
                ldsm_x4(b8[bj], b8hb + T8B + bj * 16 * ROW8);
#pragma unroll
            for (int mi = 0; mi < 4; ++mi)
#pragma unroll
                for (int jn = 0; jn < 4; ++jn) {
                    const int bj = jn >> 1, hf = jn & 1;
                    mma16832q(acc8[mi][jn], a8[mi], b8[bj][hf], b8[bj][hf + 2]);
                }
            // pass 2: Al8 x Bh8
#pragma unroll
            for (int mi = 0; mi < 4; ++mi)
                ldsm_x4(a8[mi], a8hb + T8B + mi * 16 * ROW8);
#pragma unroll
            for (int bj = 0; bj < 2; ++bj)
                ldsm_x4(b8[bj], b8hb + bj * 16 * ROW8);
#pragma unroll
            for (int mi = 0; mi < 4; ++mi)
#pragma unroll
                for (int jn = 0; jn < 4; ++jn) {
                    const int bj = jn >> 1, hf = jn & 1;
                    mma16832q(acc8[mi][jn], a8[mi], b8[bj][hf], b8[bj][hf + 2]);
                }
        }

        // fp16 hh pass: 2x k16.
#pragma unroll
        for (int ks = 0; ks < 2; ++ks) {
            uint32_t ah[4][4], bh[2][4];
            const uint32_t abase = sbase + s * STAGE_SC
                + (wm * 64 + lrow) * ROWB + ks * 32 + lcol * 16;
#pragma unroll
            for (int mi = 0; mi < 4; ++mi)
                ldsm_x4(ah[mi], abase + mi * 16 * ROWB);
            const uint32_t bbase = sbase + s * STAGE_SC + TILE_B
                + (wn * 32 + lrow) * ROWB + ks * 32 + lcol * 16;
#pragma unroll
            for (int bj = 0; bj < 2; ++bj)
                ldsm_x4(bh[bj], bbase + bj * 16 * ROWB);
#pragma unroll
            for (int mi = 0; mi < 4; ++mi)
#pragma unroll
                for (int jn = 0; jn < 4; ++jn) {
                    const int bj = jn >> 1, hf = jn & 1;
                    mma16816h(acc[mi][jn], ah[mi], bh[bj][hf], bh[bj][hf + 2]);
                }
        }
    }

    // Fold scaled fp8 cross accumulators into the main accumulators.
#pragma unroll
    for (int mi = 0; mi < 4; ++mi)
#pragma unroll
        for (int jn = 0; jn < 4; ++jn)
#pragma unroll
            for (int v = 0; v < 4; ++v)
                acc[mi][jn][v] += acc8[mi][jn][v] * FP8_INVSCALE;

    const int g = lane >> 2, cq = (lane & 3) * 2;
#pragma unroll
    for (int mi = 0; mi < 4; ++mi) {
#pragma unroll
        for (int jn = 0; jn < 4; ++jn) {
            const int r0w = row0 + wm * 64 + mi * 16 + g;
            const int cc = col0 + wn * 32 + jn * 8 + cq;
            *(float2*)(C + (size_t)r0w * N + cc)
                = make_float2(acc[mi][jn][0], acc[mi][jn][1]);
            *(float2*)(C + (size_t)(r0w + 8) * N + cc)
                = make_float2(acc[mi][jn][2], acc[mi][jn][3]);
        }
    }

    // Softmax pass-1 from registers (per-column max/sumexp over 128 rows).
    cp_wait<0>();
    __syncthreads();
    float* SM_M = (float*)sm;            // [2][128]
    float* SM_S = (float*)(sm + 1024);   // [2][128]
#pragma unroll
    for (int jn = 0; jn < 4; ++jn) {
        float m0 = -1e30f, m1 = -1e30f;
#pragma unroll
        for (int mi = 0; mi < 4; ++mi) {
            m0 = fmaxf(m0, fmaxf(acc[mi][jn][0], acc[mi][jn][2]));
            m1 = fmaxf(m1, fmaxf(acc[mi][jn][1], acc[mi][jn][3]));
        }
        float s0 = 0.f, s1 = 0.f;
#pragma unroll
        for (int mi = 0; mi < 4; ++mi) {
            s0 += __expf(acc[mi][jn][0] - m0) + __expf(acc[mi][jn][2] - m0);
            s1 += __expf(acc[mi][jn][1] - m1) + __expf(acc[mi][jn][3] - m1);
        }
#pragma unroll
        for (int o = 4; o < 32; o <<= 1) {
            float mo = __shfl_xor_sync(0xffffffffu, m0, o);
            float so = __shfl_xor_sync(0xffffffffu, s0, o);
            float nm = fmaxf(m0, mo);
            s0 = s0 * __expf(m0 - nm) + so * __expf(mo - nm); m0 = nm;
            mo = __shfl_xor_sync(0xffffffffu, m1, o);
            so = __shfl_xor_sync(0xffffffffu, s1, o);
            nm = fmaxf(m1, mo);
            s1 = s1 * __expf(m1 - nm) + so * __expf(mo - nm); m1 = nm;
        }
        if ((lane >> 2) == 0) {
            int cit = wn * 32 + jn * 8 + (lane & 3) * 2;
            SM_M[wm * 128 + cit]     = m0;  SM_S[wm * 128 + cit]     = s0;
            SM_M[wm * 128 + cit + 1] = m1;  SM_S[wm * 128 + cit + 1] = s1;
        }
    }
    __syncthreads();
    if (tid < 128) {
        float ma = SM_M[tid], mb = SM_M[128 + tid];
        float sa = SM_S[tid], sb = SM_S[128 + tid];
        float nm = fmaxf(ma, mb);
        float s = sa * __expf(ma - nm) + sb * __expf(mb - nm);
        g_pm[(size_t)blockIdx.y * cNK + col0 + tid] = nm;
        g_ps[(size_t)blockIdx.y * cNK + col0 + tid] = s;
    }
}

// === 1-pass fp16 GEMM: C = A * B^T, fp32 accumulate (fused GEMM) ===
static const int STAGE_B1 = 2 * TILE_B;        // A, B
static const int SMEM_1P  = 3 * STAGE_B1;      // 61440

__global__ __launch_bounds__(256, 1)
void mma_gemm_f16(const __half* __restrict__ A, const __half* __restrict__ B,
                  float* __restrict__ C, int M, int N, int K)
{
    extern __shared__ char sm[];
    const uint32_t sbase = smem_to_u32(sm);

    const int tid = threadIdx.x;
    const int wid = tid >> 5, lane = tid & 31;
    const int wm = wid >> 2, wn = wid & 3;
    const int row0 = blockIdx.y * 128, col0 = blockIdx.x * 128;

    const __half* srcs[2] = { A + (size_t)row0 * K, B + (size_t)col0 * K };

    const int NT = K >> 5;

    auto issue_loads = [&](int kt, int s) {
        const int k0 = kt << 5;
#pragma unroll
        for (int i = 0; i < 4; ++i) {
            int q = tid + i * 256;
            int t = q >> 9, idx = q & 511;
            int row = idx >> 2, c = idx & 3;
            const __half* g = srcs[t] + (size_t)row * K + k0 + c * 8;
            uint32_t d = sbase + s * STAGE_B1 + t * TILE_B + row * ROWB + c * 16;
            cp_async16(d, g);
        }
    };

    issue_loads(0, 0); cp_commit();
    issue_loads(1, 1); cp_commit();

    float acc[4][4][4];
#pragma unroll
    for (int i = 0; i < 4; ++i)
#pragma unroll
        for (int j = 0; j < 4; ++j)
#pragma unroll
            for (int v = 0; v < 4; ++v) acc[i][j][v] = 0.f;

    const int lrow = lane & 15, lcol = lane >> 4;

    for (int kt = 0; kt < NT; ++kt) {
        const int s = kt % 3;
        cp_wait<1>();
        __syncthreads();
        if (kt + 2 < NT) issue_loads(kt + 2, (kt + 2) % 3);
        cp_commit();

#pragma unroll
        for (int ks = 0; ks < 2; ++ks) {
            uint32_t aa[4][4], bb[2][4];
            const uint32_t abase = sbase + s * STAGE_B1
                + (wm * 64 + lrow) * ROWB + ks * 32 + lcol * 16;
#pragma unroll
            for (int mi = 0; mi < 4; ++mi)
                ldsm_x4(aa[mi], abase + mi * 16 * ROWB);
            const uint32_t bbase = sbase + s * STAGE_B1 + TILE_B
                + (wn * 32 + lrow) * ROWB + ks * 32 + lcol * 16;
#pragma unroll
            for (int bj = 0; bj < 2; ++bj)
                ldsm_x4(bb[bj], bbase + bj * 16 * ROWB);
#pragma unroll
            for (int mi = 0; mi < 4; ++mi) {
#pragma unroll
                for (int jn = 0; jn < 4; ++jn) {
                    const int bj = jn >> 1, hf = jn & 1;
                    mma16816h(acc[mi][jn], aa[mi], bb[bj][hf], bb[bj][hf + 2]);
                }
            }
        }
    }

    const int g = lane >> 2, cq = (lane & 3) * 2;
#pragma unroll
    for (int mi = 0; mi < 4; ++mi) {
#pragma unroll
        for (int jn = 0; jn < 4; ++jn) {
            const int r0w = row0 + wm * 64 + mi * 16 + g;
            const int cc = col0 + wn * 32 + jn * 8 + cq;
            *(float2*)(C + (size_t)r0w * N + cc)
                = make_float2(acc[mi][jn][0], acc[mi][jn][1]);
            *(float2*)(C + (size_t)(r0w + 8) * N + cc)
                = make_float2(acc[mi][jn][2], acc[mi][jn][3]);
        }
    }
}

// ---------------------------------------------------------------------------
// Column softmax (axis 0): pass 1 fused into scores GEMM; pass 2 reduces
// chunk stats; pass 3 split: fp16 emit (critical path) + fp32 in-place
// normalize (overlapped with the fused GEMM on the side stream).
// ---------------------------------------------------------------------------
__global__ void softmax_pass2() {
    const int j = blockIdx.x * 256 + threadIdx.x;
    float m = -1e30f, s = 0.f;
#pragma unroll 8
    for (int c = 0; c < CHUNKS; ++c) {
        float pm = g_pm[(size_t)c * cNK + j];
        float ps = g_ps[(size_t)c * cNK + j];
        float nm = fmaxf(m, pm);
        s = s * __expf(m - nm) + ps * __expf(pm - nm);
        m = nm;
    }
    g_m[j] = m;
    g_rs[j] = 1.f / s;
}

__global__ void softmax_emit_f16(const float* __restrict__ sc,
                                 __half* __restrict__ at) {
    const int j4 = (blockIdx.x * 256 + threadIdx.x) * 4;
    const size_t i = blockIdx.y;
    float4 x = *(const float4*)(sc + i * cNK + j4);
    float4 m = *(const float4*)(&g_m[j4]);
    float4 rs = *(const float4*)(&g_rs[j4]);
    float e0 = __expf(x.x - m.x) * rs.x;
    float e1 = __expf(x.y - m.y) * rs.y;
    float e2 = __expf(x.z - m.z) * rs.z;
    float e3 = __expf(x.w - m.w) * rs.w;
    size_t off = i * cNK + j4;
    *(__half2*)(at + off)     = __floats2half2_rn(e0, e1);
    *(__half2*)(at + off + 2) = __floats2half2_rn(e2, e3);
}

__global__ void softmax_norm_f32(float* __restrict__ sc) {
    const int j4 = (blockIdx.x * 256 + threadIdx.x) * 4;
    const size_t i = blockIdx.y;
    float4 x = *(float4*)(sc + i * cNK + j4);
    float4 m = *(const float4*)(&g_m[j4]);
    float4 rs = *(const float4*)(&g_rs[j4]);
    x.x = __expf(x.x - m.x) * rs.x;
    x.y = __expf(x.y - m.y) * rs.y;
    x.z = __expf(x.z - m.z) * rs.z;
    x.w = __expf(x.w - m.w) * rs.w;
    *(float4*)(sc + i * cNK + j4) = x;
}

// ---------------------------------------------------------------------------
// Launch
// ---------------------------------------------------------------------------
extern "C" void kernel_launch(void* const* d_in, const int* in_sizes, int n_in,
                              void* d_out, int out_size)
{
    const float* Xs = (const float*)d_in[0];
    const float* Xk = (const float*)d_in[1];
    const float* Ws = (const float*)d_in[2];
    const float* bs = (const float*)d_in[3];
    const float* Wk = (const float*)d_in[4];
    const float* bk = (const float*)d_in[5];

    float* attns = (float*)d_out;
    float* fused = attns + (size_t)cNS * cNK;

    __nv_bfloat16 *Xsh, *Xsl, *Xkh, *Xkl, *Wsh, *Wsl, *Wkh, *Wkl;
    __half *Sh, *Kh, *VT, *At;
    uint8_t *Sh8, *Sl8, *Kh8, *Kl8;
    cudaGetSymbolAddress((void**)&Xsh, g_Xs_h); cudaGetSymbolAddress((void**)&Xsl, g_Xs_l);
    cudaGetSymbolAddress((void**)&Xkh, g_Xk_h); cudaGetSymbolAddress((void**)&Xkl, g_Xk_l);
    cudaGetSymbolAddress((void**)&Wsh, g_Ws_h); cudaGetSymbolAddress((void**)&Wsl, g_Ws_l);
    cudaGetSymbolAddress((void**)&Wkh, g_Wk_h); cudaGetSymbolAddress((void**)&Wkl, g_Wk_l);
    cudaGetSymbolAddress((void**)&Sh,  g_S_h);
    cudaGetSymbolAddress((void**)&Sh8, g_S_h8); cudaGetSymbolAddress((void**)&Sl8, g_S_l8);
    cudaGetSymbolAddress((void**)&Kh,  g_K_h);
    cudaGetSymbolAddress((void**)&Kh8, g_K_h8); cudaGetSymbolAddress((void**)&Kl8, g_K_l8);
    cudaGetSymbolAddress((void**)&VT,  g_VT);
    cudaGetSymbolAddress((void**)&At,  g_At);

    cudaFuncSetAttribute(mma_gemm_proj,
                         cudaFuncAttributeMaxDynamicSharedMemorySize, SMEM_3P);
    cudaFuncSetAttribute(mma_gemm_scores,
                         cudaFuncAttributeMaxDynamicSharedMemorySize, SMEM_SC);
    cudaFuncSetAttribute(mma_gemm_f16,
                         cudaFuncAttributeMaxDynamicSharedMemorySize, SMEM_1P);

    // Side stream + events (fork/join pattern proven graph-capture legal).
    static bool s_init = false;
    static bool s_ok = false;
    static cudaStream_t s_side;
    static cudaEvent_t evFork, evJoin, evFork2, evJoin2;
    if (!s_init) {
        s_init = true;
        s_ok = (cudaStreamCreateWithFlags(&s_side, cudaStreamNonBlocking) == cudaSuccess)
            && (cudaEventCreateWithFlags(&evFork,  cudaEventDisableTiming) == cudaSuccess)
            && (cudaEventCreateWithFlags(&evJoin,  cudaEventDisableTiming) == cudaSuccess)
            && (cudaEventCreateWithFlags(&evFork2, cudaEventDisableTiming) == cudaSuccess)
            && (cudaEventCreateWithFlags(&evJoin2, cudaEventDisableTiming) == cudaSuccess);
    }
    cudaStream_t sd = s_ok ? s_side : (cudaStream_t)0;

    // Main stream: Xs / Ws splits (feed S-projection)
    {
        size_t n;
        n = (size_t)cNS * cHID; split_kernel<<<(unsigned)(n / 1024), 256>>>(Xs, Xsh, Xsl, n);
        n = (size_t)cHID * cHID; split_kernel<<<(unsigned)(n / 1024), 256>>>(Ws, Wsh, Wsl, n);
    }

    // Side stream: Xk split + V^T (single read of Xk), Wk split, K-projection.
    if (s_ok) {
        cudaEventRecord(evFork, 0);
        cudaStreamWaitEvent(s_side, evFork, 0);
    }
    split_transpose_kernel<<<dim3(cKED / 32, cNK / 32), dim3(32, 8), 0, sd>>>(
        Xk, Xkh, Xkl, VT, cNK, cKED);
    {
        size_t n = (size_t)cHID * cKED;
        split_kernel<<<(unsigned)(n / 1024), 256, 0, sd>>>(Wk, Wkh, Wkl, n);
    }
    mma_gemm_proj<<<dim3(cHID / 128, cNK / 128), 256, SMEM_3P, sd>>>(
        Xkh, Xkl, Wkh, Wkl, bk, Kh, Kh8, Kl8, cNK, cHID, cKED);
    if (s_ok) cudaEventRecord(evJoin, s_side);

    // S = Xs @ Ws^T + bs  -> fp16 + fp8 planes  [8192, 1024]  (main stream)
    mma_gemm_proj<<<dim3(cHID / 128, cNS / 128), 256, SMEM_3P>>>(
        Xsh, Xsl, Wsh, Wsl, bs, Sh, Sh8, Sl8, cNS, cHID, cHID);

    if (s_ok) cudaStreamWaitEvent(0, evJoin, 0);

    // scores = S @ K^T -> raw fp32 into attns region (d_out); epilogue emits
    // softmax chunk stats. hh pass fp16 k16, cross passes e4m3 k32.
    mma_gemm_scores<<<dim3(cNK / 128, cNS / 128), 256, SMEM_SC>>>(
        Sh, Sh8, Sl8, Kh, Kh8, Kl8, attns, cNS, cNK, cHID);

    // pass 2 (global stats) + fp16 emit (critical path)
    softmax_pass2<<<cNK / 256, 256>>>();
    softmax_emit_f16<<<dim3(cNK / 1024, cNS), 256>>>(attns, At);

    // fp32 normalize in place, overlapped with the fused GEMM.
    if (s_ok) {
        cudaEventRecord(evFork2, 0);
        cudaStreamWaitEvent(s_side, evFork2, 0);
        softmax_norm_f32<<<dim3(cNK / 1024, cNS), 256, 0, s_side>>>(attns);
        cudaEventRecord(evJoin2, s_side);
    } else {
        softmax_norm_f32<<<dim3(cNK / 1024, cNS), 256>>>(attns);
    }

    // fused = attns @ V = At @ VT^T  [8192, 2048], 1-pass fp16  (main stream)
    mma_gemm_f16<<<dim3(cKED / 128, cNS / 128), 256, SMEM_1P>>>(
        At, VT, fused, cNS, cKED, cNK);

    // Join side stream so the captured graph is well-formed.
    if (s_ok) cudaStreamWaitEvent(0, evJoin2, 0);
}

// round 16
// speedup vs baseline: 1.1446x; 1.1446x over previous
#include <cuda_runtime.h>
#include <cuda_bf16.h>
#include <cuda_fp16.h>
#include <stdint.h>

// ---------------------------------------------------------------------------
// Problem dims
// ---------------------------------------------------------------------------
static const int cNS  = 8192;
static const int cNK  = 8192;
static const int cHID = 1024;
static const int cKED = 2048;
static const int CHUNKS = 64;  // softmax row chunks = one 128-row CTA tile each

// ---------------------------------------------------------------------------
// Scratch (__device__ globals; allocation-free)
// ---------------------------------------------------------------------------
__device__ __nv_bfloat16 g_Xs_h[(size_t)cNS * cHID];
__device__ __nv_bfloat16 g_Xs_l[(size_t)cNS * cHID];
__device__ __nv_bfloat16 g_Xk_h[(size_t)cNK * cKED];
__device__ __nv_bfloat16 g_Xk_l[(size_t)cNK * cKED];
__device__ __nv_bfloat16 g_Ws_h[(size_t)cHID * cHID];
__device__ __nv_bfloat16 g_Ws_l[(size_t)cHID * cHID];
__device__ __nv_bfloat16 g_Wk_h[(size_t)cHID * cKED];
__device__ __nv_bfloat16 g_Wk_l[(size_t)cHID * cKED];
__device__ __half g_S_h[(size_t)cNS * cHID];           // S split planes (fp16)
__device__ __half g_S_l[(size_t)cNS * cHID];
__device__ __half g_K_h[(size_t)cNK * cHID];           // K split planes (fp16)
__device__ __half g_K_l[(size_t)cNK * cHID];
__device__ __half g_VT[(size_t)cKED * cNK];            // V^T fp16 [2048, 8192]
__device__ __half g_At[(size_t)cNS * cNK];             // attns fp16 (single plane)
__device__ float g_pm[(size_t)CHUNKS * cNK];
__device__ float g_ps[(size_t)CHUNKS * cNK];
__device__ float g_m[cNK];
__device__ float g_rs[cNK];

// ---------------------------------------------------------------------------
// Helpers
// ---------------------------------------------------------------------------
__device__ __forceinline__ uint32_t smem_to_u32(const void* p) {
    uint32_t a;
    asm("{ .reg .u64 t; cvta.to.shared.u64 t, %1; cvt.u32.u64 %0, t; }"
        : "=r"(a) : "l"(p));
    return a;
}

__device__ __forceinline__ void cp_async16(uint32_t smem_addr, const void* gptr) {
    asm volatile("cp.async.cg.shared.global [%0], [%1], 16;\n"
                 :: "r"(smem_addr), "l"(__cvta_generic_to_global(gptr)));
}
__device__ __forceinline__ void cp_commit() {
    asm volatile("cp.async.commit_group;\n" ::: "memory");
}
template <int N>
__device__ __forceinline__ void cp_wait() {
    asm volatile("cp.async.wait_group %0;\n" :: "n"(N) : "memory");
}

__device__ __forceinline__ void ldsm_x4(uint32_t (&r)[4], uint32_t addr) {
    asm volatile("ldmatrix.sync.aligned.m8n8.x4.shared.b16 {%0,%1,%2,%3}, [%4];\n"
                 : "=r"(r[0]), "=r"(r[1]), "=r"(r[2]), "=r"(r[3]) : "r"(addr));
}

// bf16 in, fp32 acc
__device__ __forceinline__ void mma16816(float (&c)[4], const uint32_t (&a)[4],
                                         uint32_t b0, uint32_t b1) {
    asm volatile(
        "mma.sync.aligned.m16n8k16.row.col.f32.bf16.bf16.f32 "
        "{%0,%1,%2,%3}, {%4,%5,%6,%7}, {%8,%9}, {%0,%1,%2,%3};\n"
        : "+f"(c[0]), "+f"(c[1]), "+f"(c[2]), "+f"(c[3])
        : "r"(a[0]), "r"(a[1]), "r"(a[2]), "r"(a[3]), "r"(b0), "r"(b1));
}

// fp16 in, fp32 acc
__device__ __forceinline__ void mma16816h(float (&c)[4], const uint32_t (&a)[4],
                                          uint32_t b0, uint32_t b1) {
    asm volatile(
        "mma.sync.aligned.m16n8k16.row.col.f32.f16.f16.f32 "
        "{%0,%1,%2,%3}, {%4,%5,%6,%7}, {%8,%9}, {%0,%1,%2,%3};\n"
        : "+f"(c[0]), "+f"(c[1]), "+f"(c[2]), "+f"(c[3])
        : "r"(a[0]), "r"(a[1]), "r"(a[2]), "r"(a[3]), "r"(b0), "r"(b1));
}

__device__ __forceinline__ void split1(float x, __nv_bfloat16& h, __nv_bfloat16& l) {
    h = __float2bfloat16(x);
    l = __float2bfloat16(x - __bfloat162float(h));
}
__device__ __forceinline__ void split1h(float x, __half& h, __half& l) {
    h = __float2half(x);
    l = __float2half(x - __half2float(h));
}

// ---------------------------------------------------------------------------
// Split / fused split+transpose preprocessing
// ---------------------------------------------------------------------------
__global__ void split_kernel(const float* __restrict__ in,
                             __nv_bfloat16* __restrict__ hi,
                             __nv_bfloat16* __restrict__ lo, size_t n) {
    size_t i = ((size_t)blockIdx.x * 256 + threadIdx.x) * 4;
    if (i >= n) return;
    float4 v = *(const float4*)(in + i);
    __nv_bfloat16 h0, h1, h2, h3, l0, l1, l2, l3;
    split1(v.x, h0, l0); split1(v.y, h1, l1);
    split1(v.z, h2, l2); split1(v.w, h3, l3);
    *(__nv_bfloat162*)(hi + i)     = __nv_bfloat162(h0, h1);
    *(__nv_bfloat162*)(hi + i + 2) = __nv_bfloat162(h2, h3);
    *(__nv_bfloat162*)(lo + i)     = __nv_bfloat162(l0, l1);
    *(__nv_bfloat162*)(lo + i + 2) = __nv_bfloat162(l2, l3);
}

// Read Xk once: emit bf16 hi/lo planes (row-major) + fp16 V^T (transposed).
__global__ void split_transpose_kernel(const float* __restrict__ in,
                                       __nv_bfloat16* __restrict__ hi,
                                       __nv_bfloat16* __restrict__ lo,
                                       __half* __restrict__ vt,
                                       int R, int C) {
    __shared__ float t[32][33];
    int c0 = blockIdx.x * 32, r0 = blockIdx.y * 32;
    int tx = threadIdx.x, ty = threadIdx.y;
#pragma unroll
    for (int j = 0; j < 4; ++j) {
        float v = in[(size_t)(r0 + ty + j * 8) * C + c0 + tx];
        t[ty + j * 8][tx] = v;
        __nv_bfloat16 h, l; split1(v, h, l);
        size_t off = (size_t)(r0 + ty + j * 8) * C + c0 + tx;
        hi[off] = h; lo[off] = l;
    }
    __syncthreads();
#pragma unroll
    for (int j = 0; j < 4; ++j)
        vt[(size_t)(c0 + ty + j * 8) * R + r0 + tx] = __float2half(t[tx][ty + j * 8]);
}

// ---------------------------------------------------------------------------
// Common GEMM geometry: 128x128 CTA tile, BK=32, 8 warps (2x4), warp tile
// 64x32, 80B-padded SMEM rows (conflict-free ldsm).
// 3-pass kernels: 2-STAGE pipeline + 2 CTAs/SM (epilogue overlap).
// ---------------------------------------------------------------------------
static const int ROWB    = 80;                 // 64B data + 16B pad
static const int TILE_B  = 128 * ROWB;         // 10240 B per plane-tile
static const int STAGE_B3 = 4 * TILE_B;        // Ah, Al, Bh, Bl
static const int SMEM_2ST = 2 * STAGE_B3;      // 81920 -> 2 CTAs/SM

// === Projection GEMM (bf16 in, fp32 acc, 3 passes): C = (Ah+Al)(Bh+Bl)^T + b
//     Epilogue emits fp16 hi/lo planes. 2-stage, 2 CTAs/SM. ===
__global__ __launch_bounds__(256, 2)
void mma_gemm_proj(const __nv_bfloat16* __restrict__ Ah, const __nv_bfloat16* __restrict__ Al,
                   const __nv_bfloat16* __restrict__ Bh, const __nv_bfloat16* __restrict__ Bl,
                   const float* __restrict__ bias,
                   __half* __restrict__ Ch, __half* __restrict__ Cl,
                   int M, int N, int K)
{
    extern __shared__ char sm[];
    const uint32_t sbase = smem_to_u32(sm);

    const int tid = threadIdx.x;
    const int wid = tid >> 5, lane = tid & 31;
    const int wm = wid >> 2, wn = wid & 3;      // 2 x 4 warp grid
    const int row0 = blockIdx.y * 128, col0 = blockIdx.x * 128;

    const __nv_bfloat16* srcs[4] = {
        Ah + (size_t)row0 * K, Al + (size_t)row0 * K,
        Bh + (size_t)col0 * K, Bl + (size_t)col0 * K };

    const int NT = K >> 5;

    auto issue_loads = [&](int kt, int s) {
        const int k0 = kt << 5;
#pragma unroll
        for (int i = 0; i < 8; ++i) {
            int q = tid + i * 256;
            int t = q >> 9, idx = q & 511;
            int row = idx >> 2, c = idx & 3;
            const __nv_bfloat16* g = srcs[t] + (size_t)row * K + k0 + c * 8;
            uint32_t d = sbase + s * STAGE_B3 + t * TILE_B + row * ROWB + c * 16;
            cp_async16(d, g);
        }
    };

    issue_loads(0, 0); cp_commit();

    float acc[4][4][4];
#pragma unroll
    for (int i = 0; i < 4; ++i)
#pragma unroll
        for (int j = 0; j < 4; ++j)
#pragma unroll
            for (int v = 0; v < 4; ++v) acc[i][j][v] = 0.f;

    const int lrow = lane & 15, lcol = lane >> 4;

    for (int kt = 0; kt < NT; ++kt) {
        const int s = kt & 1;
        cp_wait<0>();
        __syncthreads();
        if (kt + 1 < NT) { issue_loads(kt + 1, (kt + 1) & 1); cp_commit(); }

#pragma unroll
        for (int ks = 0; ks < 2; ++ks) {
            uint32_t ah[4][4], al[4][4], bh[2][4], bl[2][4];
            const uint32_t abase = sbase + s * STAGE_B3
                + (wm * 64 + lrow) * ROWB + ks * 32 + lcol * 16;
#pragma unroll
            for (int mi = 0; mi < 4; ++mi) {
                ldsm_x4(ah[mi], abase + mi * 16 * ROWB);
                ldsm_x4(al[mi], abase + mi * 16 * ROWB + TILE_B);
            }
            const uint32_t bbase = sbase + s * STAGE_B3 + 2 * TILE_B
                + (wn * 32 + lrow) * ROWB + ks * 32 + lcol * 16;
#pragma unroll
            for (int bj = 0; bj < 2; ++bj) {
                ldsm_x4(bh[bj], bbase + bj * 16 * ROWB);
                ldsm_x4(bl[bj], bbase + bj * 16 * ROWB + TILE_B);
            }
#pragma unroll
            for (int mi = 0; mi < 4; ++mi) {
#pragma unroll
                for (int jn = 0; jn < 4; ++jn) {
                    const int bj = jn >> 1, hf = jn & 1;
                    mma16816(acc[mi][jn], ah[mi], bh[bj][hf], bh[bj][hf + 2]);
                    mma16816(acc[mi][jn], ah[mi], bl[bj][hf], bl[bj][hf + 2]);
                    mma16816(acc[mi][jn], al[mi], bh[bj][hf], bh[bj][hf + 2]);
                }
            }
        }
        __syncthreads();
    }

    const int g = lane >> 2, cq = (lane & 3) * 2;
#pragma unroll
    for (int mi = 0; mi < 4; ++mi) {
#pragma unroll
        for (int jn = 0; jn < 4; ++jn) {
            const int r0w = row0 + wm * 64 + mi * 16 + g;
            const int cc = col0 + wn * 32 + jn * 8 + cq;
            float b0 = bias[cc], b1 = bias[cc + 1];
            float v0 = acc[mi][jn][0] + b0, v1 = acc[mi][jn][1] + b1;
            float v2 = acc[mi][jn][2] + b0, v3 = acc[mi][jn][3] + b1;
            __half h0, h1, h2, h3, l0, l1, l2, l3;
            split1h(v0, h0, l0); split1h(v1, h1, l1);
            split1h(v2, h2, l2); split1h(v3, h3, l3);
            size_t o0 = (size_t)r0w * N + cc;
            size_t o1 = (size_t)(r0w + 8) * N + cc;
            *(__half2*)(Ch + o0) = __halves2half2(h0, h1);
            *(__half2*)(Cl + o0) = __halves2half2(l0, l1);
            *(__half2*)(Ch + o1) = __halves2half2(h2, h3);
            *(__half2*)(Cl + o1) = __halves2half2(l2, l3);
        }
    }
}

// === Scores GEMM (fp16 in, fp32 acc, 3 passes). Writes raw fp32 scores;
//     epilogue emits softmax chunk stats. 2-stage, 2 CTAs/SM. ===
__global__ __launch_bounds__(256, 2)
void mma_gemm_scores(const __half* __restrict__ Ah, const __half* __restrict__ Al,
                     const __half* __restrict__ Bh, const __half* __restrict__ Bl,
                     float* __restrict__ C, int M, int N, int K)
{
    extern __shared__ char sm[];
    const uint32_t sbase = smem_to_u32(sm);

    const int tid = threadIdx.x;
    const int wid = tid >> 5, lane = tid & 31;
    const int wm = wid >> 2, wn = wid & 3;
    const int row0 = blockIdx.y * 128, col0 = blockIdx.x * 128;

    const __half* srcs[4] = {
        Ah + (size_t)row0 * K, Al + (size_t)row0 * K,
        Bh + (size_t)col0 * K, Bl + (size_t)col0 * K };

    const int NT = K >> 5;

    auto issue_loads = [&](int kt, int s) {
        const int k0 = kt << 5;
#pragma unroll
        for (int i = 0; i < 8; ++i) {
            int q = tid + i * 256;
            int t = q >> 9, idx = q & 511;
            int row = idx >> 2, c = idx & 3;
            const __half* g = srcs[t] + (size_t)row * K + k0 + c * 8;
            uint32_t d = sbase + s * STAGE_B3 + t * TILE_B + row * ROWB + c * 16;
            cp_async16(d, g);
        }
    };

    issue_loads(0, 0); cp_commit();

    float acc[4][4][4];
#pragma unroll
    for (int i = 0; i < 4; ++i)
#pragma unroll
        for (int j = 0; j < 4; ++j)
#pragma unroll
            for (int v = 0; v < 4; ++v) acc[i][j][v] = 0.f;

    const int lrow = lane & 15, lcol = lane >> 4;

    for (int kt = 0; kt < NT; ++kt) {
        const int s = kt & 1;
        cp_wait<0>();
        __syncthreads();
        if (kt + 1 < NT) { issue_loads(kt + 1, (kt + 1) & 1); cp_commit(); }

#pragma unroll
        for (int ks = 0; ks < 2; ++ks) {
            uint32_t ah[4][4], al[4][4], bh[2][4], bl[2][4];
            const uint32_t abase = sbase + s * STAGE_B3
                + (wm * 64 + lrow) * ROWB + ks * 32 + lcol * 16;
#pragma unroll
            for (int mi = 0; mi < 4; ++mi) {
                ldsm_x4(ah[mi], abase + mi * 16 * ROWB);
                ldsm_x4(al[mi], abase + mi * 16 * ROWB + TILE_B);
            }
            const uint32_t bbase = sbase + s * STAGE_B3 + 2 * TILE_B
                + (wn * 32 + lrow) * ROWB + ks * 32 + lcol * 16;
#pragma unroll
            for (int bj = 0; bj < 2; ++bj) {
                ldsm_x4(bh[bj], bbase + bj * 16 * ROWB);
                ldsm_x4(bl[bj], bbase + bj * 16 * ROWB + TILE_B);
            }
#pragma unroll
            for (int mi = 0; mi < 4; ++mi) {
#pragma unroll
                for (int jn = 0; jn < 4; ++jn) {
                    const int bj = jn >> 1, hf = jn & 1;
                    mma16816h(acc[mi][jn], ah[mi], bh[bj][hf], bh[bj][hf + 2]);
                    mma16816h(acc[mi][jn], ah[mi], bl[bj][hf], bl[bj][hf + 2]);
                    mma16816h(acc[mi][jn], al[mi], bh[bj][hf], bh[bj][hf + 2]);
                }
            }
        }
        __syncthreads();
    }

    const int g = lane >> 2, cq = (lane & 3) * 2;
#pragma unroll
    for (int mi = 0; mi < 4; ++mi) {
#pragma unroll
        for (int jn = 0; jn < 4; ++jn) {
            const int r0w = row0 + wm * 64 + mi * 16 + g;
            const int cc = col0 + wn * 32 + jn * 8 + cq;
            *(float2*)(C + (size_t)r0w * N + cc)
                = make_float2(acc[mi][jn][0], acc[mi][jn][1]);
            *(float2*)(C + (size_t)(r0w + 8) * N + cc)
                = make_float2(acc[mi][jn][2], acc[mi][jn][3]);
        }
    }

    // Softmax pass-1 from registers (per-column max/sumexp over 128 rows).
    __syncthreads();
    float* SM_M = (float*)sm;            // [2][128]
    float* SM_S = (float*)(sm + 1024);   // [2][128]
#pragma unroll
    for (int jn = 0; jn < 4; ++jn) {
        float m0 = -1e30f, m1 = -1e30f;
#pragma unroll
        for (int mi = 0; mi < 4; ++mi) {
            m0 = fmaxf(m0, fmaxf(acc[mi][jn][0], acc[mi][jn][2]));
            m1 = fmaxf(m1, fmaxf(acc[mi][jn][1], acc[mi][jn][3]));
        }
        float s0 = 0.f, s1 = 0.f;
#pragma unroll
        for (int mi = 0; mi < 4; ++mi) {
            s0 += __expf(acc[mi][jn][0] - m0) + __expf(acc[mi][jn][2] - m0);
            s1 += __expf(acc[mi][jn][1] - m1) + __expf(acc[mi][jn][3] - m1);
        }
#pragma unroll
        for (int o = 4; o < 32; o <<= 1) {
            float mo = __shfl_xor_sync(0xffffffffu, m0, o);
            float so = __shfl_xor_sync(0xffffffffu, s0, o);
            float nm = fmaxf(m0, mo);
            s0 = s0 * __expf(m0 - nm) + so * __expf(mo - nm); m0 = nm;
            mo = __shfl_xor_sync(0xffffffffu, m1, o);
            so = __shfl_xor_sync(0xffffffffu, s1, o);
            nm = fmaxf(m1, mo);
            s1 = s1 * __expf(m1 - nm) + so * __expf(mo - nm); m1 = nm;
        }
        if ((lane >> 2) == 0) {
            int cit = wn * 32 + jn * 8 + (lane & 3) * 2;
            SM_M[wm * 128 + cit]     = m0;  SM_S[wm * 128 + cit]     = s0;
            SM_M[wm * 128 + cit + 1] = m1;  SM_S[wm * 128 + cit + 1] = s1;
        }
    }
    __syncthreads();
    if (tid < 128) {
        float ma = SM_M[tid], mb = SM_M[128 + tid];
        float sa = SM_S[tid], sb = SM_S[128 + tid];
        float nm = fmaxf(ma, mb);
        float s = sa * __expf(ma - nm) + sb * __expf(mb - nm);
        g_pm[(size_t)blockIdx.y * cNK + col0 + tid] = nm;
        g_ps[(size_t)blockIdx.y * cNK + col0 + tid] = s;
    }
}

// === 1-pass fp16 GEMM: C = A * B^T, fp32 accumulate (fused GEMM).
//     Proven 3-stage mainloop; 61 KB smem -> 2 CTAs/SM with LB(256,2). ===
static const int STAGE_B1 = 2 * TILE_B;        // A, B
static const int SMEM_1P  = 3 * STAGE_B1;      // 61440

__global__ __launch_bounds__(256, 2)
void mma_gemm_f16(const __half* __restrict__ A, const __half* __restrict__ B,
                  float* __restrict__ C, int M, int N, int K)
{
    extern __shared__ char sm[];
    const uint32_t sbase = smem_to_u32(sm);

    const int tid = threadIdx.x;
    const int wid = tid >> 5, lane = tid & 31;
    const int wm = wid >> 2, wn = wid & 3;
    const int row0 = blockIdx.y * 128, col0 = blockIdx.x * 128;

    const __half* srcs[2] = { A + (size_t)row0 * K, B + (size_t)col0 * K };

    const int NT = K >> 5;

    auto issue_loads = [&](int kt, int s) {
        const int k0 = kt << 5;
#pragma unroll
        for (int i = 0; i < 4; ++i) {
            int q = tid + i * 256;
            int t = q >> 9, idx = q & 511;
            int row = idx >> 2, c = idx & 3;
            const __half* g = srcs[t] + (size_t)row * K + k0 + c * 8;
            uint32_t d = sbase + s * STAGE_B1 + t * TILE_B + row * ROWB + c * 16;
            cp_async16(d, g);
        }
    };

    issue_loads(0, 0); cp_commit();
    issue_loads(1, 1); cp_commit();

    float acc[4][4][4];
#pragma unroll
    for (int i = 0; i < 4; ++i)
#pragma unroll
        for (int j = 0; j < 4; ++j)
#pragma unroll
            for (int v = 0; v < 4; ++v) acc[i][j][v] = 0.f;

    const int lrow = lane & 15, lcol = lane >> 4;

    for (int kt = 0; kt < NT; ++kt) {
        const int s = kt % 3;
        cp_wait<1>();
        __syncthreads();
        if (kt + 2 < NT) issue_loads(kt + 2, (kt + 2) % 3);
        cp_commit();

#pragma unroll
        for (int ks = 0; ks < 2; ++ks) {
            uint32_t aa[4][4], bb[2][4];
            const uint32_t abase = sbase + s * STAGE_B1
                + (wm * 64 + lrow) * ROWB + ks * 32 + lcol * 16;
#pragma unroll
            for (int mi = 0; mi < 4; ++mi)
                ldsm_x4(aa[mi], abase + mi * 16 * ROWB);
            const uint32_t bbase = sbase + s * STAGE_B1 + TILE_B
                + (wn * 32 + lrow) * ROWB + ks * 32 + lcol * 16;
#pragma unroll
            for (int bj = 0; bj < 2; ++bj)
                ldsm_x4(bb[bj], bbase + bj * 16 * ROWB);
#pragma unroll
            for (int mi = 0; mi < 4; ++mi) {
#pragma unroll
                for (int jn = 0; jn < 4; ++jn) {
                    const int bj = jn >> 1, hf = jn & 1;
                    mma16816h(acc[mi][jn], aa[mi], bb[bj][hf], bb[bj][hf + 2]);
                }
            }
        }
    }

    const int g = lane >> 2, cq = (lane & 3) * 2;
#pragma unroll
    for (int mi = 0; mi < 4; ++mi) {
#pragma unroll
        for (int jn = 0; jn < 4; ++jn) {
            const int r0w = row0 + wm * 64 + mi * 16 + g;
            const int cc = col0 + wn * 32 + jn * 8 + cq;
            *(float2*)(C + (size_t)r0w * N + cc)
                = make_float2(acc[mi][jn][0], acc[mi][jn][1]);
            *(float2*)(C + (size_t)(r0w + 8) * N + cc)
                = make_float2(acc[mi][jn][2], acc[mi][jn][3]);
        }
    }
}

// ---------------------------------------------------------------------------
// Column softmax (axis 0): pass 1 fused into scores GEMM; pass 2 reduces
// chunk stats; pass 3 split: fp16 emit (critical path) + fp32 in-place
// normalize (overlapped with the fused GEMM on the side stream).
// ---------------------------------------------------------------------------
__global__ void softmax_pass2() {
    const int j = blockIdx.x * 256 + threadIdx.x;
    float m = -1e30f, s = 0.f;
#pragma unroll 8
    for (int c = 0; c < CHUNKS; ++c) {
        float pm = g_pm[(size_t)c * cNK + j];
        float ps = g_ps[(size_t)c * cNK + j];
        float nm = fmaxf(m, pm);
        s = s * __expf(m - nm) + ps * __expf(pm - nm);
        m = nm;
    }
    g_m[j] = m;
    g_rs[j] = 1.f / s;
}

__global__ void softmax_emit_f16(const float* __restrict__ sc,
                                 __half* __restrict__ at) {
    const int j4 = (blockIdx.x * 256 + threadIdx.x) * 4;
    const size_t i = blockIdx.y;
    float4 x = *(const float4*)(sc + i * cNK + j4);
    float4 m = *(const float4*)(&g_m[j4]);
    float4 rs = *(const float4*)(&g_rs[j4]);
    float e0 = __expf(x.x - m.x) * rs.x;
    float e1 = __expf(x.y - m.y) * rs.y;
    float e2 = __expf(x.z - m.z) * rs.z;
    float e3 = __expf(x.w - m.w) * rs.w;
    size_t off = i * cNK + j4;
    *(__half2*)(at + off)     = __floats2half2_rn(e0, e1);
    *(__half2*)(at + off + 2) = __floats2half2_rn(e2, e3);
}

__global__ void softmax_norm_f32(float* __restrict__ sc) {
    const int j4 = (blockIdx.x * 256 + threadIdx.x) * 4;
    const size_t i = blockIdx.y;
    float4 x = *(float4*)(sc + i * cNK + j4);
    float4 m = *(const float4*)(&g_m[j4]);
    float4 rs = *(const float4*)(&g_rs[j4]);
    x.x = __expf(x.x - m.x) * rs.x;
    x.y = __expf(x.y - m.y) * rs.y;
    x.z = __expf(x.z - m.z) * rs.z;
    x.w = __expf(x.w - m.w) * rs.w;
    *(float4*)(sc + i * cNK + j4) = x;
}

// ---------------------------------------------------------------------------
// Launch
// ---------------------------------------------------------------------------
extern "C" void kernel_launch(void* const* d_in, const int* in_sizes, int n_in,
                              void* d_out, int out_size)
{
    const float* Xs = (const float*)d_in[0];
    const float* Xk = (const float*)d_in[1];
    const float* Ws = (const float*)d_in[2];
    const float* bs = (const float*)d_in[3];
    const float* Wk = (const float*)d_in[4];
    const float* bk = (const float*)d_in[5];

    float* attns = (float*)d_out;
    float* fused = attns + (size_t)cNS * cNK;

    __nv_bfloat16 *Xsh, *Xsl, *Xkh, *Xkl, *Wsh, *Wsl, *Wkh, *Wkl;
    __half *Sh, *Sl, *Kh, *Kl, *VT, *At;
    cudaGetSymbolAddress((void**)&Xsh, g_Xs_h); cudaGetSymbolAddress((void**)&Xsl, g_Xs_l);
    cudaGetSymbolAddress((void**)&Xkh, g_Xk_h); cudaGetSymbolAddress((void**)&Xkl, g_Xk_l);
    cudaGetSymbolAddress((void**)&Wsh, g_Ws_h); cudaGetSymbolAddress((void**)&Wsl, g_Ws_l);
    cudaGetSymbolAddress((void**)&Wkh, g_Wk_h); cudaGetSymbolAddress((void**)&Wkl, g_Wk_l);
    cudaGetSymbolAddress((void**)&Sh,  g_S_h);  cudaGetSymbolAddress((void**)&Sl,  g_S_l);
    cudaGetSymbolAddress((void**)&Kh,  g_K_h);  cudaGetSymbolAddress((void**)&Kl,  g_K_l);
    cudaGetSymbolAddress((void**)&VT,  g_VT);
    cudaGetSymbolAddress((void**)&At,  g_At);

    cudaFuncSetAttribute(mma_gemm_proj,
                         cudaFuncAttributeMaxDynamicSharedMemorySize, SMEM_2ST);
    cudaFuncSetAttribute(mma_gemm_scores,
                         cudaFuncAttributeMaxDynamicSharedMemorySize, SMEM_2ST);
    cudaFuncSetAttribute(mma_gemm_f16,
                         cudaFuncAttributeMaxDynamicSharedMemorySize, SMEM_1P);

    // Side stream + events (fork/join pattern proven graph-capture legal).
    static bool s_init = false;
    static bool s_ok = false;
    static cudaStream_t s_side;
    static cudaEvent_t evFork, evJoin, evFork2, evJoin2;
    if (!s_init) {
        s_init = true;
        s_ok = (cudaStreamCreateWithFlags(&s_side, cudaStreamNonBlocking) == cudaSuccess)
            && (cudaEventCreateWithFlags(&evFork,  cudaEventDisableTiming) == cudaSuccess)
            && (cudaEventCreateWithFlags(&evJoin,  cudaEventDisableTiming) == cudaSuccess)
            && (cudaEventCreateWithFlags(&evFork2, cudaEventDisableTiming) == cudaSuccess)
            && (cudaEventCreateWithFlags(&evJoin2, cudaEventDisableTiming) == cudaSuccess);
    }
    cudaStream_t sd = s_ok ? s_side : (cudaStream_t)0;

    // Main stream: Xs / Ws splits (feed S-projection)
    {
        size_t n;
        n = (size_t)cNS * cHID; split_kernel<<<(unsigned)(n / 1024), 256>>>(Xs, Xsh, Xsl, n);
        n = (size_t)cHID * cHID; split_kernel<<<(unsigned)(n / 1024), 256>>>(Ws, Wsh, Wsl, n);
    }

    // Side stream: Xk split + V^T (single read of Xk), Wk split, K-projection.
    if (s_ok) {
        cudaEventRecord(evFork, 0);
        cudaStreamWaitEvent(s_side, evFork, 0);
    }
    split_transpose_kernel<<<dim3(cKED / 32, cNK / 32), dim3(32, 8), 0, sd>>>(
        Xk, Xkh, Xkl, VT, cNK, cKED);
    {
        size_t n = (size_t)cHID * cKED;
        split_kernel<<<(unsigned)(n / 1024), 256, 0, sd>>>(Wk, Wkh, Wkl, n);
    }
    mma_gemm_proj<<<dim3(cHID / 128, cNK / 128), 256, SMEM_2ST, sd>>>(
        Xkh, Xkl, Wkh, Wkl, bk, Kh, Kl, cNK, cHID, cKED);
    if (s_ok) cudaEventRecord(evJoin, s_side);

    // S = Xs @ Ws^T + bs  -> fp16 split planes  [8192, 1024]  (main stream)
    mma_gemm_proj<<<dim3(cHID / 128, cNS / 128), 256, SMEM_2ST>>>(
        Xsh, Xsl, Wsh, Wsl, bs, Sh, Sl, cNS, cHID, cHID);

    if (s_ok) cudaStreamWaitEvent(0, evJoin, 0);

    // scores = S @ K^T -> raw fp32 into attns region (d_out); epilogue emits
    // softmax chunk stats.
    mma_gemm_scores<<<dim3(cNK / 128, cNS / 128), 256, SMEM_2ST>>>(
        Sh, Sl, Kh, Kl, attns, cNS, cNK, cHID);

    // pass 2 (global stats) + fp16 emit (critical path)
    softmax_pass2<<<cNK / 256, 256>>>();
    softmax_emit_f16<<<dim3(cNK / 1024, cNS), 256>>>(attns, At);

    // fp32 normalize in place, overlapped with the fused GEMM.
    if (s_ok) {
        cudaEventRecord(evFork2, 0);
        cudaStreamWaitEvent(s_side, evFork2, 0);
        softmax_norm_f32<<<dim3(cNK / 1024, cNS), 256, 0, s_side>>>(attns);
        cudaEventRecord(evJoin2, s_side);
    } else {
        softmax_norm_f32<<<dim3(cNK / 1024, cNS), 256>>>(attns);
    }

    // fused = attns @ V = At @ VT^T  [8192, 2048], 1-pass fp16  (main stream)
    mma_gemm_f16<<<dim3(cKED / 128, cNS / 128), 256, SMEM_1P>>>(
        At, VT, fused, cNS, cKED, cNK);

    // Join side stream so the captured graph is well-formed.
    if (s_ok) cudaStreamWaitEvent(0, evJoin2, 0);
}